// round 13
// baseline (speedup 1.0000x reference)
#include <cuda_runtime.h>
#include <cuda_bf16.h>
#include <cstdint>

#define C_CH   128
#define HW     16384
#define BATCH  8
#define QKV_CH 384
#define NHEAD  8
#define DH     16
#define NCHUNK 4    // bands per (b,head)

// ===================== scratch ==============================================
__device__ float g_qkv  [(long)BATCH * QKV_CH * HW];
__device__ float g_qkv2 [(long)BATCH * QKV_CH * HW];
__device__ float g_part [64 * NCHUNK * 288];
__device__ float g_attn [64 * 256];
__device__ __align__(16) __nv_bfloat16 g_whi   [QKV_CH * C_CH];
__device__ __align__(16) __nv_bfloat16 g_wlo   [QKV_CH * C_CH];
__device__ __align__(16) __nv_bfloat16 g_wehi  [BATCH * C_CH * C_CH];
__device__ __align__(16) __nv_bfloat16 g_welo  [BATCH * C_CH * C_CH];

// ===================== PTX helpers ==========================================
__device__ __forceinline__ uint32_t smem_u32(const void* p) {
    uint32_t a;
    asm("{ .reg .u64 t; cvta.to.shared.u64 t, %1; cvt.u32.u64 %0, t; }" : "=r"(a) : "l"(p));
    return a;
}
__device__ __forceinline__ void ldsm_x4(uint32_t* r, uint32_t addr) {
    asm volatile("ldmatrix.sync.aligned.m8n8.x4.shared.b16 {%0,%1,%2,%3}, [%4];"
                 : "=r"(r[0]), "=r"(r[1]), "=r"(r[2]), "=r"(r[3]) : "r"(addr));
}
__device__ __forceinline__ void ldsm_x4_t(uint32_t* r, uint32_t addr) {
    asm volatile("ldmatrix.sync.aligned.m8n8.x4.trans.shared.b16 {%0,%1,%2,%3}, [%4];"
                 : "=r"(r[0]), "=r"(r[1]), "=r"(r[2]), "=r"(r[3]) : "r"(addr));
}
__device__ __forceinline__ void mma_bf16(float* d, const uint32_t* a, const uint32_t* b) {
    asm volatile(
        "mma.sync.aligned.m16n8k16.row.col.f32.bf16.bf16.f32 "
        "{%0,%1,%2,%3}, {%4,%5,%6,%7}, {%8,%9}, {%0,%1,%2,%3};"
        : "+f"(d[0]), "+f"(d[1]), "+f"(d[2]), "+f"(d[3])
        : "r"(a[0]), "r"(a[1]), "r"(a[2]), "r"(a[3]), "r"(b[0]), "r"(b[1]));
}
__device__ __forceinline__ void cp_async16(uint32_t dst, const void* src) {
    asm volatile("cp.async.ca.shared.global [%0], [%1], 16;" :: "r"(dst), "l"(src));
}
#define CP_COMMIT() asm volatile("cp.async.commit_group;" ::: "memory")
#define CP_WAIT(n)  asm volatile("cp.async.wait_group %0;" :: "n"(n) : "memory")

__device__ __forceinline__ uint32_t split_hi2(float x, float y, float& rx, float& ry) {
    const __nv_bfloat16 hx = __float2bfloat16(x);
    const __nv_bfloat16 hy = __float2bfloat16(y);
    rx = x - __bfloat162float(hx);
    ry = y - __bfloat162float(hy);
    __nv_bfloat162 p; p.x = hx; p.y = hy;
    return *(uint32_t*)&p;
}
__device__ __forceinline__ uint32_t pack_bf2(float x, float y) {
    __nv_bfloat162 p; p.x = __float2bfloat16(x); p.y = __float2bfloat16(y);
    return *(uint32_t*)&p;
}

// ===================== split kernel (weights) ================================
__global__ void __launch_bounds__(256) cvt_split(
    const float* __restrict__ in,
    __nv_bfloat16* __restrict__ hi, __nv_bfloat16* __restrict__ lo)
{
    const long i4 = (long)blockIdx.x * 256 + threadIdx.x;
    const float4 v = ((const float4*)in)[i4];
    float lx, ly, lz, lw;
    const uint32_t h0 = split_hi2(v.x, v.y, lx, ly);
    const uint32_t h1 = split_hi2(v.z, v.w, lz, lw);
    ((uint2*)hi)[i4] = make_uint2(h0, h1);
    ((uint2*)lo)[i4] = make_uint2(pack_bf2(lx, ly), pack_bf2(lz, lw));
}

// ===================== unified GEMM (round-8 config) =========================
#define WS      136
#define XS      136
#define S_WHI   0
#define S_WLO   34816
#define S_XHI   69632
#define S_XLO   78336
#define SM_GEMM 87040

template<bool GATED>
__global__ void __launch_bounds__(256, 2) gemm_cvt(
    const __nv_bfloat16* __restrict__ Whi_g, const __nv_bfloat16* __restrict__ Wlo_g,
    long wz,
    const float* __restrict__ Xg, long xz,
    const float* __restrict__ Ig, long iz,
    float* __restrict__ Cg, int Mw)
{
    extern __shared__ char sm[];
    const uint32_t smb = smem_u32(sm);

    const int tid  = threadIdx.x;
    const int lane = tid & 31;
    const int wid  = tid >> 5;
    const int wm   = wid >> 2;
    const int wn   = wid & 3;
    const int n0   = blockIdx.x * 128;
    const int m0   = blockIdx.y * 128;
    const int z    = blockIdx.z;

    const __nv_bfloat16* Whi = Whi_g + (long)z * wz;
    const __nv_bfloat16* Wlo = Wlo_g + (long)z * wz;
    const float* X = Xg + (long)z * xz;
    const float* I = GATED ? (Ig + (long)z * iz) : nullptr;
    float* C = Cg + (long)z * (long)Mw * HW;

    #pragma unroll
    for (int t = 0; t < 16; t++) {
        const int lin = t * 256 + tid;
        const int spl = lin >> 11;
        const int row = (lin >> 4) & 127;
        const int seg = lin & 15;
        const __nv_bfloat16* src = (spl ? Wlo : Whi) + (long)(m0 + row) * 128 + seg * 8;
        const uint32_t dst = smb + (spl ? S_WLO : S_WHI) + (row * WS + seg * 8) * 2;
        cp_async16(dst, src);
    }
    CP_COMMIT();

    float acc[4][4][4];
    #pragma unroll
    for (int i = 0; i < 4; i++)
        #pragma unroll
        for (int j = 0; j < 4; j++)
            #pragma unroll
            for (int r = 0; r < 4; r++) acc[i][j][r] = 0.f;

    const int a_row = (lane & 7) + ((lane >> 3) & 1) * 8;
    const int a_col = (lane >> 4) * 8;
    const int b_row = (lane & 7) + ((lane >> 3) & 1) * 8;
    const int b_col = (lane >> 4) * 8;

    const int r0 = tid >> 5;
    const int c4 = (tid & 31) * 4;

    float4 xs[4], is_[4];
    #pragma unroll
    for (int rr = 0; rr < 4; rr++) {
        const int grow = r0 + rr * 8;
        xs[rr] = *(const float4*)(X + (long)grow * HW + n0 + c4);
        if (GATED) is_[rr] = *(const float4*)(I + (long)grow * HW + n0 + c4);
    }
    CP_WAIT(0);

    #pragma unroll
    for (int kc = 0; kc < 4; kc++) {
        #pragma unroll
        for (int rr = 0; rr < 4; rr++) {
            float4 v = xs[rr];
            if (GATED) { v.x *= is_[rr].x; v.y *= is_[rr].y; v.z *= is_[rr].z; v.w *= is_[rr].w; }
            float lx, ly, lz, lw;
            const uint32_t h0 = split_hi2(v.x, v.y, lx, ly);
            const uint32_t h1 = split_hi2(v.z, v.w, lz, lw);
            const int row = r0 + rr * 8;
            const uint32_t off = (uint32_t)(row * XS + c4) * 2;
            *(uint2*)(sm + S_XHI + off) = make_uint2(h0, h1);
            *(uint2*)(sm + S_XLO + off) = make_uint2(pack_bf2(lx, ly), pack_bf2(lz, lw));
        }
        __syncthreads();

        if (kc < 3) {
            #pragma unroll
            for (int rr = 0; rr < 4; rr++) {
                const int grow = (kc + 1) * 32 + r0 + rr * 8;
                xs[rr] = *(const float4*)(X + (long)grow * HW + n0 + c4);
                if (GATED) is_[rr] = *(const float4*)(I + (long)grow * HW + n0 + c4);
            }
        }

        #pragma unroll
        for (int ks = 0; ks < 2; ks++) {
            const int kk  = ks * 16;
            const int kkg = kc * 32 + kk;
            uint32_t a[4][4], bh[2][4], bl[2][4];

            #pragma unroll
            for (int u = 0; u < 2; u++) {
                const int r = kk + b_row;
                const int c = wn * 32 + u * 16 + b_col;
                ldsm_x4_t(bh[u], smb + S_XHI + (r * XS + c) * 2);
                ldsm_x4_t(bl[u], smb + S_XLO + (r * XS + c) * 2);
            }
            #pragma unroll
            for (int i = 0; i < 4; i++) {
                const int r = wm * 64 + i * 16 + a_row;
                ldsm_x4(a[i], smb + S_WHI + (r * WS + kkg + a_col) * 2);
            }
            #pragma unroll
            for (int i = 0; i < 4; i++)
                #pragma unroll
                for (int j = 0; j < 4; j++)
                    mma_bf16(acc[i][j], a[i], &bh[j >> 1][(j & 1) * 2]);
            #pragma unroll
            for (int i = 0; i < 4; i++)
                #pragma unroll
                for (int j = 0; j < 4; j++)
                    mma_bf16(acc[i][j], a[i], &bl[j >> 1][(j & 1) * 2]);
            #pragma unroll
            for (int i = 0; i < 4; i++) {
                const int r = wm * 64 + i * 16 + a_row;
                ldsm_x4(a[i], smb + S_WLO + (r * WS + kkg + a_col) * 2);
            }
            #pragma unroll
            for (int i = 0; i < 4; i++)
                #pragma unroll
                for (int j = 0; j < 4; j++)
                    mma_bf16(acc[i][j], a[i], &bh[j >> 1][(j & 1) * 2]);
        }
        __syncthreads();
    }

    const int mw = m0 + wm * 64;
    const int nw = n0 + wn * 32;
    #pragma unroll
    for (int i = 0; i < 4; i++) {
        #pragma unroll
        for (int j = 0; j < 4; j++) {
            const int row0 = mw + i * 16 + (lane >> 2);
            const int col  = nw + j * 8 + (lane & 3) * 2;
            *(float2*)&C[(long)row0 * HW + col]       = make_float2(acc[i][j][0], acc[i][j][1]);
            *(float2*)&C[(long)(row0 + 8) * HW + col] = make_float2(acc[i][j][2], acc[i][j][3]);
        }
    }
}

// ===================== depthwise 3x3 — v channels only =======================
__global__ void __launch_bounds__(256) dwconv_v(
    const float* __restrict__ qkv, const float* __restrict__ w,
    float* __restrict__ qkv2)
{
    __shared__ float s[34][128];

    const int bc = blockIdx.y;               // 0..BATCH*C_CH-1
    const int b  = bc >> 7, c = bc & 127;
    const int gch = b * QKV_CH + 2 * C_CH + c;
    const int wch = 2 * C_CH + c;
    const int y0 = blockIdx.x * 32;
    const int tid = threadIdx.x;
    const float* ip = qkv + (long)gch * HW;

    for (int t = tid; t < 1088; t += 256) {
        const int r  = t >> 5;
        const int c4 = (t & 31) * 4;
        const int gy = y0 - 1 + r;
        float4 v = make_float4(0.f, 0.f, 0.f, 0.f);
        if (gy >= 0 && gy < 128) v = *(const float4*)&ip[gy * 128 + c4];
        *(float4*)&s[r][c4] = v;
    }

    const float* wp = w + wch * 9;
    const float w00 = wp[0], w01 = wp[1], w02 = wp[2];
    const float w10 = wp[3], w11 = wp[4], w12 = wp[5];
    const float w20 = wp[6], w21 = wp[7], w22 = wp[8];
    __syncthreads();

    const int x = (tid & 31) * 4;
    #pragma unroll
    for (int h = 0; h < 4; h++) {
        const int oy = (tid >> 5) + h * 8;
        float o0 = 0.f, o1 = 0.f, o2 = 0.f, o3 = 0.f;
        #pragma unroll
        for (int dy = 0; dy < 3; dy++) {
            const float* row = s[oy + dy];
            const float4 v = *(const float4*)&row[x];
            const float vl = (x > 0)   ? row[x - 1] : 0.f;
            const float vr = (x < 124) ? row[x + 4] : 0.f;
            const float wa = (dy == 0) ? w00 : (dy == 1) ? w10 : w20;
            const float wb = (dy == 0) ? w01 : (dy == 1) ? w11 : w21;
            const float wc = (dy == 0) ? w02 : (dy == 1) ? w12 : w22;
            o0 += vl  * wa + v.x * wb + v.y * wc;
            o1 += v.x * wa + v.y * wb + v.z * wc;
            o2 += v.y * wa + v.z * wb + v.w * wc;
            o3 += v.z * wa + v.w * wb + vr  * wc;
        }
        *(float4*)&qkv2[(long)gch * HW + (y0 + oy) * 128 + x] = make_float4(o0, o1, o2, o3);
    }
}

// ===================== fused dwconv(q,k) + gram ==============================
// Block: one (b,head) x 32-row band. 4-row raw ring, 2-row conv chunks.
// Conv outputs never leave SMEM; gram partials + norms out per band.
#define GC_RNG   0                         // float rng[32][4][132]
#define GC_CVB   67584                     // float cvb[32][2][132]
#define GC_SMEM  101376

__global__ void __launch_bounds__(256, 2) gramconv(
    const float* __restrict__ qkv, const float* __restrict__ wdw,
    float* __restrict__ partials)
{
    extern __shared__ char smc[];
    float* rng = (float*)(smc + GC_RNG);    // [ch][slot][132] -> ch*528 + slot*132 + x
    float* cvb = (float*)(smc + GC_CVB);    // [ch][ridx][132] -> ch*264 + ridx*132 + x

    const int bh = blockIdx.y;
    const int b  = bh >> 3, hd = bh & 7;
    const int y0 = blockIdx.x * 32;
    const int tid = threadIdx.x;

    // channel -> global pointer/weight index (ch 0..15 = q, 16..31 = k)
    const float* qb = qkv + (long)b * QKV_CH * HW + (long)(hd * DH) * HW;
    const float* kb = qb + (long)C_CH * HW;

    // conv thread mapping: ch, 16-col segment
    const int cch = tid >> 3;               // 0..31
    const int seg = tid & 7;                // 0..7
    const int x0  = seg * 16;
    const int wch = (cch < 16) ? (hd * DH + cch) : (C_CH + hd * DH + (cch - 16));
    float wv[9];
    #pragma unroll
    for (int i = 0; i < 9; i++) wv[i] = wdw[wch * 9 + i];

    // gram thread mapping
    const int tt = tid & 15;
    const int jj = (tid >> 4) & 3;
    const int ii = tid >> 6;

    float acc[4][4];
    #pragma unroll
    for (int a = 0; a < 4; a++)
        #pragma unroll
        for (int c = 0; c < 4; c++) acc[a][c] = 0.f;
    float nq[4] = {0.f, 0.f, 0.f, 0.f};
    float nk[4] = {0.f, 0.f, 0.f, 0.f};

    for (int it = 0; it < 16; it++) {
        const int ya = y0 + it * 2;

        // ---- load raw rows into ring ----
        // one row = 32 ch x 128 floats = 1024 float4 = 4 loop trips at 256 thr
        const int nrows = (it == 0) ? 4 : 2;
        const int yfirst = (it == 0) ? (ya - 1) : (ya + 1);
        for (int l = 0; l < nrows * 4; l++) {
            const int lin  = l * 256 + tid;
            const int ridx = lin >> 10;              // row within batch
            const int rem  = lin & 1023;
            const int ch   = rem >> 5;
            const int c4   = (rem & 31) * 4;
            const int y    = yfirst + ridx;
            float4 v = make_float4(0.f, 0.f, 0.f, 0.f);
            if (y >= 0 && y < 128) {
                const float* src = (ch < 16) ? (qb + (long)ch * HW)
                                             : (kb + (long)(ch - 16) * HW);
                v = *(const float4*)(src + y * 128 + c4);
            }
            *(float4*)&rng[ch * 528 + (y & 3) * 132 + c4] = v;
        }
        __syncthreads();

        // ---- conv: 2 rows x 16 cols for this thread's channel ----
        #pragma unroll
        for (int ridx = 0; ridx < 2; ridx++) {
            const int y = ya + ridx;
            float o[16];
            #pragma unroll
            for (int x = 0; x < 16; x++) o[x] = 0.f;
            #pragma unroll
            for (int dy = 0; dy < 3; dy++) {
                const int yy = y - 1 + dy;
                const float* row = &rng[cch * 528 + (yy & 3) * 132];
                float vals[18];
                vals[0]  = (x0 > 0) ? row[x0 - 1] : 0.f;
                #pragma unroll
                for (int q4 = 0; q4 < 4; q4++) {
                    const float4 v = *(const float4*)&row[x0 + q4 * 4];
                    vals[1 + q4 * 4] = v.x; vals[2 + q4 * 4] = v.y;
                    vals[3 + q4 * 4] = v.z; vals[4 + q4 * 4] = v.w;
                }
                vals[17] = (x0 + 16 < 128) ? row[x0 + 16] : 0.f;
                const float wa = wv[dy * 3], wb = wv[dy * 3 + 1], wc = wv[dy * 3 + 2];
                #pragma unroll
                for (int x = 0; x < 16; x++)
                    o[x] += vals[x] * wa + vals[x + 1] * wb + vals[x + 2] * wc;
            }
            #pragma unroll
            for (int q4 = 0; q4 < 4; q4++)
                *(float4*)&cvb[cch * 264 + ridx * 132 + x0 + q4 * 4] =
                    make_float4(o[q4 * 4], o[q4 * 4 + 1], o[q4 * 4 + 2], o[q4 * 4 + 3]);
        }
        __syncthreads();

        // ---- gram accumulate over 256 positions (2 rows x 128) ----
        #pragma unroll
        for (int u = 0; u < 4; u++) {
            const int pos4 = (tt + u * 16) * 4;      // 0..252
            const int prow = pos4 >> 7;
            const int px   = pos4 & 127;
            float4 q4[4], k4[4];
            #pragma unroll
            for (int r = 0; r < 4; r++)
                q4[r] = *(const float4*)&cvb[(ii * 4 + r) * 264 + prow * 132 + px];
            #pragma unroll
            for (int r = 0; r < 4; r++)
                k4[r] = *(const float4*)&cvb[(16 + jj * 4 + r) * 264 + prow * 132 + px];
            #pragma unroll
            for (int a = 0; a < 4; a++)
                #pragma unroll
                for (int c = 0; c < 4; c++)
                    acc[a][c] += q4[a].x * k4[c].x + q4[a].y * k4[c].y
                               + q4[a].z * k4[c].z + q4[a].w * k4[c].w;
            if (jj == 0) {
                #pragma unroll
                for (int r = 0; r < 4; r++)
                    nq[r] += q4[r].x * q4[r].x + q4[r].y * q4[r].y
                           + q4[r].z * q4[r].z + q4[r].w * q4[r].w;
            }
            if (ii == 0) {
                #pragma unroll
                for (int r = 0; r < 4; r++)
                    nk[r] += k4[r].x * k4[r].x + k4[r].y * k4[r].y
                           + k4[r].z * k4[r].z + k4[r].w * k4[r].w;
            }
        }
        // next iteration's ring load only overwrites slots whose conv reads
        // completed before the post-conv __syncthreads above.
    }

    // butterfly reduce over tt
    #pragma unroll
    for (int m = 1; m < 16; m <<= 1) {
        #pragma unroll
        for (int a = 0; a < 4; a++)
            #pragma unroll
            for (int c = 0; c < 4; c++)
                acc[a][c] += __shfl_xor_sync(0xFFFFFFFFu, acc[a][c], m);
        #pragma unroll
        for (int r = 0; r < 4; r++) {
            nq[r] += __shfl_xor_sync(0xFFFFFFFFu, nq[r], m);
            nk[r] += __shfl_xor_sync(0xFFFFFFFFu, nk[r], m);
        }
    }

    float* p = partials + ((long)bh * NCHUNK + blockIdx.x) * 288;
    if (tt == 0) {
        #pragma unroll
        for (int a = 0; a < 4; a++)
            #pragma unroll
            for (int c = 0; c < 4; c++)
                p[(ii * 4 + a) * 16 + jj * 4 + c] = acc[a][c];
        if (jj == 0) {
            #pragma unroll
            for (int r = 0; r < 4; r++) p[256 + ii * 4 + r] = nq[r];
        }
        if (ii == 0) {
            #pragma unroll
            for (int r = 0; r < 4; r++) p[256 + 16 + jj * 4 + r] = nk[r];
        }
    }
}

// ===================== softmax ==============================================
__global__ void __launch_bounds__(256) attn_softmax(
    const float* __restrict__ partials, const float* __restrict__ temperature,
    float* __restrict__ attn)
{
    const int bh = blockIdx.x;
    const int hd = bh & 7;
    __shared__ float S[256];
    __shared__ float qn[16], kn[16];
    const int tid = threadIdx.x;
    float s = 0.f;
    #pragma unroll
    for (int c = 0; c < NCHUNK; c++)
        s += partials[((long)bh * NCHUNK + c) * 288 + tid];
    S[tid] = s;
    if (tid < 32) {
        float ns = 0.f;
        #pragma unroll
        for (int c = 0; c < NCHUNK; c++)
            ns += partials[((long)bh * NCHUNK + c) * 288 + 256 + tid];
        const float nv = fmaxf(sqrtf(ns), 1e-12f);
        if (tid < 16) qn[tid] = nv; else kn[tid - 16] = nv;
    }
    __syncthreads();
    if (tid < 16) {
        const int   i  = tid;
        const float tp = temperature[hd];
        float lg[16];
        float mx = -1e30f;
        #pragma unroll
        for (int j = 0; j < 16; j++) {
            lg[j] = S[i * 16 + j] / (qn[i] * kn[j]) * tp;
            mx = fmaxf(mx, lg[j]);
        }
        float sum = 0.f;
        #pragma unroll
        for (int j = 0; j < 16; j++) { lg[j] = expf(lg[j] - mx); sum += lg[j]; }
        const float inv = 1.f / sum;
        #pragma unroll
        for (int j = 0; j < 16; j++)
            attn[(long)bh * 256 + i * 16 + j] = lg[j] * inv;
    }
}

// ===================== Weff = W_proj @ blockdiag(attn) ======================
__global__ void __launch_bounds__(256) weff_build(
    const float* __restrict__ wproj, const float* __restrict__ attn,
    __nv_bfloat16* __restrict__ whi, __nv_bfloat16* __restrict__ wlo)
{
    const int bh = blockIdx.x;
    const int h  = bh & 7, z = bh >> 3;
    __shared__ float at[16][16];
    __shared__ float wp[128][17];
    const int tid = threadIdx.x;

    at[tid >> 4][tid & 15] = attn[(long)bh * 256 + tid];
    #pragma unroll
    for (int t = 0; t < 8; t++) {
        const int idx = t * 256 + tid;
        const int o = idx >> 4, i = idx & 15;
        wp[o][i] = wproj[o * 128 + h * 16 + i];
    }
    __syncthreads();

    const int o  = tid >> 1;
    const int jb = (tid & 1) * 8;
    #pragma unroll
    for (int jj = 0; jj < 8; jj++) {
        const int j = jb + jj;
        float acc = 0.f;
        #pragma unroll
        for (int i = 0; i < 16; i++) acc += wp[o][i] * at[i][j];
        const __nv_bfloat16 hh = __float2bfloat16(acc);
        const __nv_bfloat16 ll = __float2bfloat16(acc - __bfloat162float(hh));
        const long oidx = ((long)z * 128 + o) * 128 + h * 16 + j;
        whi[oidx] = hh;
        wlo[oidx] = ll;
    }
}

// ===================== launch ===============================================
extern "C" void kernel_launch(void* const* d_in, const int* in_sizes, int n_in,
                              void* d_out, int out_size)
{
    const float* x_in   = (const float*)d_in[0];
    const float* illu   = (const float*)d_in[1];
    const float* w_qkv  = (const float*)d_in[2];
    const float* w_dw   = (const float*)d_in[3];
    const float* w_proj = (const float*)d_in[4];
    const float* temp   = (const float*)d_in[5];
    float* out = (float*)d_out;

    float *qkv, *qkv2, *part, *attn;
    __nv_bfloat16 *whi, *wlo, *wehi, *welo;
    cudaGetSymbolAddress((void**)&qkv,  g_qkv);
    cudaGetSymbolAddress((void**)&qkv2, g_qkv2);
    cudaGetSymbolAddress((void**)&part, g_part);
    cudaGetSymbolAddress((void**)&attn, g_attn);
    cudaGetSymbolAddress((void**)&whi,  g_whi);
    cudaGetSymbolAddress((void**)&wlo,  g_wlo);
    cudaGetSymbolAddress((void**)&wehi, g_wehi);
    cudaGetSymbolAddress((void**)&welo, g_welo);

    cudaFuncSetAttribute(gemm_cvt<false>, cudaFuncAttributeMaxDynamicSharedMemorySize, SM_GEMM);
    cudaFuncSetAttribute(gemm_cvt<true>,  cudaFuncAttributeMaxDynamicSharedMemorySize, SM_GEMM);
    cudaFuncSetAttribute(gramconv, cudaFuncAttributeMaxDynamicSharedMemorySize, GC_SMEM);

    // 0) pre-split qkv weights
    cvt_split<<<QKV_CH * C_CH / 1024, 256>>>(w_qkv, whi, wlo);
    // 1) qkv = w_qkv @ x
    gemm_cvt<false><<<dim3(HW / 128, QKV_CH / 128, BATCH), 256, SM_GEMM>>>(
        whi, wlo, 0L, x_in, (long)C_CH * HW, nullptr, 0L, qkv, QKV_CH);
    // 2) depthwise 3x3 — v channels only
    dwconv_v<<<dim3(4, BATCH * C_CH), 256>>>(qkv, w_dw, qkv2);
    // 3) fused dwconv(q,k) + gram partials + norms
    gramconv<<<dim3(NCHUNK, 64), 256, GC_SMEM>>>(qkv, w_dw, part);
    // 4) softmax
    attn_softmax<<<64, 256>>>(part, temp, attn);
    // 5) Weff[z] = W_proj @ blockdiag(attn[z])
    weff_build<<<64, 256>>>(w_proj, attn, wehi, welo);
    // 6) out = Weff[z] @ (v .* illu)
    gemm_cvt<true><<<dim3(HW / 128, 1, BATCH), 256, SM_GEMM>>>(
        wehi, welo, (long)C_CH * C_CH,
        qkv2 + 2L * C_CH * HW, (long)QKV_CH * HW,
        illu, (long)C_CH * HW, out, C_CH);
}

// round 14
// speedup vs baseline: 1.1556x; 1.1556x over previous
#include <cuda_runtime.h>
#include <cuda_bf16.h>
#include <cstdint>

#define C_CH   128
#define HW     16384
#define BATCH  8
#define QKV_CH 384
#define NHEAD  8
#define DH     16
#define NCHUNK 16

// ===================== scratch ==============================================
__device__ float g_qkv  [(long)BATCH * QKV_CH * HW];
__device__ float g_qkv2 [(long)BATCH * QKV_CH * HW];
__device__ float g_part [64 * NCHUNK * 288];
__device__ float g_attn [64 * 256];
__device__ __align__(16) __nv_bfloat16 g_whi   [QKV_CH * C_CH];
__device__ __align__(16) __nv_bfloat16 g_wlo   [QKV_CH * C_CH];
__device__ __align__(16) __nv_bfloat16 g_wehi  [BATCH * C_CH * C_CH];
__device__ __align__(16) __nv_bfloat16 g_welo  [BATCH * C_CH * C_CH];

// ===================== PTX helpers ==========================================
__device__ __forceinline__ uint32_t smem_u32(const void* p) {
    uint32_t a;
    asm("{ .reg .u64 t; cvta.to.shared.u64 t, %1; cvt.u32.u64 %0, t; }" : "=r"(a) : "l"(p));
    return a;
}
__device__ __forceinline__ void ldsm_x4(uint32_t* r, uint32_t addr) {
    asm volatile("ldmatrix.sync.aligned.m8n8.x4.shared.b16 {%0,%1,%2,%3}, [%4];"
                 : "=r"(r[0]), "=r"(r[1]), "=r"(r[2]), "=r"(r[3]) : "r"(addr));
}
__device__ __forceinline__ void ldsm_x4_t(uint32_t* r, uint32_t addr) {
    asm volatile("ldmatrix.sync.aligned.m8n8.x4.trans.shared.b16 {%0,%1,%2,%3}, [%4];"
                 : "=r"(r[0]), "=r"(r[1]), "=r"(r[2]), "=r"(r[3]) : "r"(addr));
}
__device__ __forceinline__ void mma_bf16(float* d, const uint32_t* a, const uint32_t* b) {
    asm volatile(
        "mma.sync.aligned.m16n8k16.row.col.f32.bf16.bf16.f32 "
        "{%0,%1,%2,%3}, {%4,%5,%6,%7}, {%8,%9}, {%0,%1,%2,%3};"
        : "+f"(d[0]), "+f"(d[1]), "+f"(d[2]), "+f"(d[3])
        : "r"(a[0]), "r"(a[1]), "r"(a[2]), "r"(a[3]), "r"(b[0]), "r"(b[1]));
}
__device__ __forceinline__ void cp_async16(uint32_t dst, const void* src) {
    asm volatile("cp.async.ca.shared.global [%0], [%1], 16;" :: "r"(dst), "l"(src));
}
#define CP_COMMIT() asm volatile("cp.async.commit_group;" ::: "memory")
#define CP_WAIT(n)  asm volatile("cp.async.wait_group %0;" :: "n"(n) : "memory")

__device__ __forceinline__ uint32_t split_hi2(float x, float y, float& rx, float& ry) {
    const __nv_bfloat16 hx = __float2bfloat16(x);
    const __nv_bfloat16 hy = __float2bfloat16(y);
    rx = x - __bfloat162float(hx);
    ry = y - __bfloat162float(hy);
    __nv_bfloat162 p; p.x = hx; p.y = hy;
    return *(uint32_t*)&p;
}
__device__ __forceinline__ uint32_t pack_bf2(float x, float y) {
    __nv_bfloat162 p; p.x = __float2bfloat16(x); p.y = __float2bfloat16(y);
    return *(uint32_t*)&p;
}

// ===================== split kernel (weights) ================================
__global__ void __launch_bounds__(256) cvt_split(
    const float* __restrict__ in,
    __nv_bfloat16* __restrict__ hi, __nv_bfloat16* __restrict__ lo)
{
    const long i4 = (long)blockIdx.x * 256 + threadIdx.x;
    const float4 v = ((const float4*)in)[i4];
    float lx, ly, lz, lw;
    const uint32_t h0 = split_hi2(v.x, v.y, lx, ly);
    const uint32_t h1 = split_hi2(v.z, v.w, lz, lw);
    ((uint2*)hi)[i4] = make_uint2(h0, h1);
    ((uint2*)lo)[i4] = make_uint2(pack_bf2(lx, ly), pack_bf2(lz, lw));
}

// ===================== unified GEMM (round-8 config) =========================
#define WS      136
#define XS      136
#define S_WHI   0
#define S_WLO   34816
#define S_XHI   69632
#define S_XLO   78336
#define SM_GEMM 87040

template<bool GATED>
__global__ void __launch_bounds__(256, 2) gemm_cvt(
    const __nv_bfloat16* __restrict__ Whi_g, const __nv_bfloat16* __restrict__ Wlo_g,
    long wz,
    const float* __restrict__ Xg, long xz,
    const float* __restrict__ Ig, long iz,
    float* __restrict__ Cg, int Mw)
{
    extern __shared__ char sm[];
    const uint32_t smb = smem_u32(sm);

    const int tid  = threadIdx.x;
    const int lane = tid & 31;
    const int wid  = tid >> 5;
    const int wm   = wid >> 2;
    const int wn   = wid & 3;
    const int n0   = blockIdx.x * 128;
    const int m0   = blockIdx.y * 128;
    const int z    = blockIdx.z;

    const __nv_bfloat16* Whi = Whi_g + (long)z * wz;
    const __nv_bfloat16* Wlo = Wlo_g + (long)z * wz;
    const float* X = Xg + (long)z * xz;
    const float* I = GATED ? (Ig + (long)z * iz) : nullptr;
    float* C = Cg + (long)z * (long)Mw * HW;

    #pragma unroll
    for (int t = 0; t < 16; t++) {
        const int lin = t * 256 + tid;
        const int spl = lin >> 11;
        const int row = (lin >> 4) & 127;
        const int seg = lin & 15;
        const __nv_bfloat16* src = (spl ? Wlo : Whi) + (long)(m0 + row) * 128 + seg * 8;
        const uint32_t dst = smb + (spl ? S_WLO : S_WHI) + (row * WS + seg * 8) * 2;
        cp_async16(dst, src);
    }
    CP_COMMIT();

    float acc[4][4][4];
    #pragma unroll
    for (int i = 0; i < 4; i++)
        #pragma unroll
        for (int j = 0; j < 4; j++)
            #pragma unroll
            for (int r = 0; r < 4; r++) acc[i][j][r] = 0.f;

    const int a_row = (lane & 7) + ((lane >> 3) & 1) * 8;
    const int a_col = (lane >> 4) * 8;
    const int b_row = (lane & 7) + ((lane >> 3) & 1) * 8;
    const int b_col = (lane >> 4) * 8;

    const int r0 = tid >> 5;
    const int c4 = (tid & 31) * 4;

    float4 xs[4], is_[4];
    #pragma unroll
    for (int rr = 0; rr < 4; rr++) {
        const int grow = r0 + rr * 8;
        xs[rr] = *(const float4*)(X + (long)grow * HW + n0 + c4);
        if (GATED) is_[rr] = *(const float4*)(I + (long)grow * HW + n0 + c4);
    }
    CP_WAIT(0);

    #pragma unroll
    for (int kc = 0; kc < 4; kc++) {
        #pragma unroll
        for (int rr = 0; rr < 4; rr++) {
            float4 v = xs[rr];
            if (GATED) { v.x *= is_[rr].x; v.y *= is_[rr].y; v.z *= is_[rr].z; v.w *= is_[rr].w; }
            float lx, ly, lz, lw;
            const uint32_t h0 = split_hi2(v.x, v.y, lx, ly);
            const uint32_t h1 = split_hi2(v.z, v.w, lz, lw);
            const int row = r0 + rr * 8;
            const uint32_t off = (uint32_t)(row * XS + c4) * 2;
            *(uint2*)(sm + S_XHI + off) = make_uint2(h0, h1);
            *(uint2*)(sm + S_XLO + off) = make_uint2(pack_bf2(lx, ly), pack_bf2(lz, lw));
        }
        __syncthreads();

        if (kc < 3) {
            #pragma unroll
            for (int rr = 0; rr < 4; rr++) {
                const int grow = (kc + 1) * 32 + r0 + rr * 8;
                xs[rr] = *(const float4*)(X + (long)grow * HW + n0 + c4);
                if (GATED) is_[rr] = *(const float4*)(I + (long)grow * HW + n0 + c4);
            }
        }

        #pragma unroll
        for (int ks = 0; ks < 2; ks++) {
            const int kk  = ks * 16;
            const int kkg = kc * 32 + kk;
            uint32_t a[4][4], bh[2][4], bl[2][4];

            #pragma unroll
            for (int u = 0; u < 2; u++) {
                const int r = kk + b_row;
                const int c = wn * 32 + u * 16 + b_col;
                ldsm_x4_t(bh[u], smb + S_XHI + (r * XS + c) * 2);
                ldsm_x4_t(bl[u], smb + S_XLO + (r * XS + c) * 2);
            }
            #pragma unroll
            for (int i = 0; i < 4; i++) {
                const int r = wm * 64 + i * 16 + a_row;
                ldsm_x4(a[i], smb + S_WHI + (r * WS + kkg + a_col) * 2);
            }
            #pragma unroll
            for (int i = 0; i < 4; i++)
                #pragma unroll
                for (int j = 0; j < 4; j++)
                    mma_bf16(acc[i][j], a[i], &bh[j >> 1][(j & 1) * 2]);
            #pragma unroll
            for (int i = 0; i < 4; i++)
                #pragma unroll
                for (int j = 0; j < 4; j++)
                    mma_bf16(acc[i][j], a[i], &bl[j >> 1][(j & 1) * 2]);
            #pragma unroll
            for (int i = 0; i < 4; i++) {
                const int r = wm * 64 + i * 16 + a_row;
                ldsm_x4(a[i], smb + S_WLO + (r * WS + kkg + a_col) * 2);
            }
            #pragma unroll
            for (int i = 0; i < 4; i++)
                #pragma unroll
                for (int j = 0; j < 4; j++)
                    mma_bf16(acc[i][j], a[i], &bh[j >> 1][(j & 1) * 2]);
        }
        __syncthreads();
    }

    const int mw = m0 + wm * 64;
    const int nw = n0 + wn * 32;
    #pragma unroll
    for (int i = 0; i < 4; i++) {
        #pragma unroll
        for (int j = 0; j < 4; j++) {
            const int row0 = mw + i * 16 + (lane >> 2);
            const int col  = nw + j * 8 + (lane & 3) * 2;
            *(float2*)&C[(long)row0 * HW + col]       = make_float2(acc[i][j][0], acc[i][j][1]);
            *(float2*)&C[(long)(row0 + 8) * HW + col] = make_float2(acc[i][j][2], acc[i][j][3]);
        }
    }
}

// ===================== depthwise 3x3 (32 rows/block, all 384 channels) =======
__global__ void __launch_bounds__(256) dwconv3x3(
    const float* __restrict__ in, const float* __restrict__ w, float* __restrict__ out)
{
    __shared__ float s[34][128];

    const int bc = blockIdx.y;
    const int y0 = blockIdx.x * 32;
    const int ch = bc % QKV_CH;
    const int tid = threadIdx.x;
    const float* ip = in + (long)bc * HW;

    for (int t = tid; t < 1088; t += 256) {
        const int r  = t >> 5;
        const int c4 = (t & 31) * 4;
        const int gy = y0 - 1 + r;
        float4 v = make_float4(0.f, 0.f, 0.f, 0.f);
        if (gy >= 0 && gy < 128) v = *(const float4*)&ip[gy * 128 + c4];
        *(float4*)&s[r][c4] = v;
    }

    const float* wp = w + ch * 9;
    const float w00 = wp[0], w01 = wp[1], w02 = wp[2];
    const float w10 = wp[3], w11 = wp[4], w12 = wp[5];
    const float w20 = wp[6], w21 = wp[7], w22 = wp[8];
    __syncthreads();

    const int x = (tid & 31) * 4;
    #pragma unroll
    for (int h = 0; h < 4; h++) {
        const int oy = (tid >> 5) + h * 8;
        float o0 = 0.f, o1 = 0.f, o2 = 0.f, o3 = 0.f;
        #pragma unroll
        for (int dy = 0; dy < 3; dy++) {
            const float* row = s[oy + dy];
            const float4 v = *(const float4*)&row[x];
            const float vl = (x > 0)   ? row[x - 1] : 0.f;
            const float vr = (x < 124) ? row[x + 4] : 0.f;
            const float wa = (dy == 0) ? w00 : (dy == 1) ? w10 : w20;
            const float wb = (dy == 0) ? w01 : (dy == 1) ? w11 : w21;
            const float wc = (dy == 0) ? w02 : (dy == 1) ? w12 : w22;
            o0 += vl  * wa + v.x * wb + v.y * wc;
            o1 += v.x * wa + v.y * wb + v.z * wc;
            o2 += v.y * wa + v.z * wb + v.w * wc;
            o3 += v.z * wa + v.w * wb + vr  * wc;
        }
        *(float4*)&out[(long)bc * HW + (y0 + oy) * 128 + x] = make_float4(o0, o1, o2, o3);
    }
}

// ===================== gram partials (cp.async double-buffered) ==============
// smem: 2 stages x (q[16][132] + k[16][132]) = 33792 B
#define GR_STG  16896          // bytes per stage (q + k)
#define GR_K    8448           // k offset within stage
#define GR_SM   33792

__global__ void __launch_bounds__(256) gram16(
    const float* __restrict__ qkv2, float* __restrict__ partials)
{
    extern __shared__ char gsm[];
    const uint32_t gsb = smem_u32(gsm);

    const int bh = blockIdx.y;
    const int b  = bh >> 3, hd = bh & 7;
    const int n0 = blockIdx.x * 1024;
    const float* qg = qkv2 + (long)b * QKV_CH * HW + (long)hd * DH * HW + n0;
    const float* kg = qg + (long)C_CH * HW;

    const int tid = threadIdx.x;
    const int tt = tid & 15;
    const int jj = (tid >> 4) & 3;
    const int ii = tid >> 6;

    // staging: each thread copies 2 float4 per tensor per chunk
    const int sr = tid >> 4;               // 0..15 (row)
    const int sc = (tid & 15) * 8;         // 0,8,...,120 (col, 8 floats = 2x16B)

    auto load_stage = [&](int stg, int t0) {
        const uint32_t base = gsb + (uint32_t)stg * GR_STG;
        const uint32_t qoff = base + (sr * 132 + sc) * 4;
        const uint32_t koff = base + GR_K + (sr * 132 + sc) * 4;
        cp_async16(qoff,      qg + (long)sr * HW + t0 + sc);
        cp_async16(qoff + 16, qg + (long)sr * HW + t0 + sc + 4);
        cp_async16(koff,      kg + (long)sr * HW + t0 + sc);
        cp_async16(koff + 16, kg + (long)sr * HW + t0 + sc + 4);
    };

    float acc[4][4];
    #pragma unroll
    for (int a = 0; a < 4; a++)
        #pragma unroll
        for (int c = 0; c < 4; c++) acc[a][c] = 0.f;
    float nq[4] = {0.f, 0.f, 0.f, 0.f};
    float nk[4] = {0.f, 0.f, 0.f, 0.f};

    load_stage(0, 0);
    CP_COMMIT();

    #pragma unroll
    for (int cidx = 0; cidx < 8; cidx++) {
        if (cidx < 7) {
            load_stage((cidx + 1) & 1, (cidx + 1) * 128);
            CP_COMMIT();
            CP_WAIT(1);
        } else {
            CP_WAIT(0);
        }
        __syncthreads();

        const float* qs = (const float*)(gsm + (cidx & 1) * GR_STG);
        const float* ks = (const float*)(gsm + (cidx & 1) * GR_STG + GR_K);

        #pragma unroll
        for (int u = 0; u < 2; u++) {
            const int c4 = (tt + u * 16) * 4;
            float4 q4[4], k4[4];
            #pragma unroll
            for (int r = 0; r < 4; r++) q4[r] = *(const float4*)&qs[(ii * 4 + r) * 132 + c4];
            #pragma unroll
            for (int r = 0; r < 4; r++) k4[r] = *(const float4*)&ks[(jj * 4 + r) * 132 + c4];
            #pragma unroll
            for (int a = 0; a < 4; a++)
                #pragma unroll
                for (int c = 0; c < 4; c++)
                    acc[a][c] += q4[a].x * k4[c].x + q4[a].y * k4[c].y
                               + q4[a].z * k4[c].z + q4[a].w * k4[c].w;
            if (jj == 0) {
                #pragma unroll
                for (int r = 0; r < 4; r++)
                    nq[r] += q4[r].x * q4[r].x + q4[r].y * q4[r].y
                           + q4[r].z * q4[r].z + q4[r].w * q4[r].w;
            }
            if (ii == 0) {
                #pragma unroll
                for (int r = 0; r < 4; r++)
                    nk[r] += k4[r].x * k4[r].x + k4[r].y * k4[r].y
                           + k4[r].z * k4[r].z + k4[r].w * k4[r].w;
            }
        }
        __syncthreads();   // stage consumed before cp.async (issued next iter) overwrites it
    }

    #pragma unroll
    for (int m = 1; m < 16; m <<= 1) {
        #pragma unroll
        for (int a = 0; a < 4; a++)
            #pragma unroll
            for (int c = 0; c < 4; c++)
                acc[a][c] += __shfl_xor_sync(0xFFFFFFFFu, acc[a][c], m);
        #pragma unroll
        for (int r = 0; r < 4; r++) {
            nq[r] += __shfl_xor_sync(0xFFFFFFFFu, nq[r], m);
            nk[r] += __shfl_xor_sync(0xFFFFFFFFu, nk[r], m);
        }
    }

    float* p = partials + ((long)bh * NCHUNK + blockIdx.x) * 288;
    if (tt == 0) {
        #pragma unroll
        for (int a = 0; a < 4; a++)
            #pragma unroll
            for (int c = 0; c < 4; c++)
                p[(ii * 4 + a) * 16 + jj * 4 + c] = acc[a][c];
        if (jj == 0) {
            #pragma unroll
            for (int r = 0; r < 4; r++) p[256 + ii * 4 + r] = nq[r];
        }
        if (ii == 0) {
            #pragma unroll
            for (int r = 0; r < 4; r++) p[256 + 16 + jj * 4 + r] = nk[r];
        }
    }
}

// ===================== softmax ==============================================
__global__ void __launch_bounds__(256) attn_softmax(
    const float* __restrict__ partials, const float* __restrict__ temperature,
    float* __restrict__ attn)
{
    const int bh = blockIdx.x;
    const int hd = bh & 7;
    __shared__ float S[256];
    __shared__ float qn[16], kn[16];
    const int tid = threadIdx.x;
    float s = 0.f;
    #pragma unroll
    for (int c = 0; c < NCHUNK; c++)
        s += partials[((long)bh * NCHUNK + c) * 288 + tid];
    S[tid] = s;
    if (tid < 32) {
        float ns = 0.f;
        #pragma unroll
        for (int c = 0; c < NCHUNK; c++)
            ns += partials[((long)bh * NCHUNK + c) * 288 + 256 + tid];
        const float nv = fmaxf(sqrtf(ns), 1e-12f);
        if (tid < 16) qn[tid] = nv; else kn[tid - 16] = nv;
    }
    __syncthreads();
    if (tid < 16) {
        const int   i  = tid;
        const float tp = temperature[hd];
        float lg[16];
        float mx = -1e30f;
        #pragma unroll
        for (int j = 0; j < 16; j++) {
            lg[j] = S[i * 16 + j] / (qn[i] * kn[j]) * tp;
            mx = fmaxf(mx, lg[j]);
        }
        float sum = 0.f;
        #pragma unroll
        for (int j = 0; j < 16; j++) { lg[j] = expf(lg[j] - mx); sum += lg[j]; }
        const float inv = 1.f / sum;
        #pragma unroll
        for (int j = 0; j < 16; j++)
            attn[(long)bh * 256 + i * 16 + j] = lg[j] * inv;
    }
}

// ===================== Weff = W_proj @ blockdiag(attn) ======================
__global__ void __launch_bounds__(256) weff_build(
    const float* __restrict__ wproj, const float* __restrict__ attn,
    __nv_bfloat16* __restrict__ whi, __nv_bfloat16* __restrict__ wlo)
{
    const int bh = blockIdx.x;
    const int h  = bh & 7, z = bh >> 3;
    __shared__ float at[16][16];
    __shared__ float wp[128][17];
    const int tid = threadIdx.x;

    at[tid >> 4][tid & 15] = attn[(long)bh * 256 + tid];
    #pragma unroll
    for (int t = 0; t < 8; t++) {
        const int idx = t * 256 + tid;
        const int o = idx >> 4, i = idx & 15;
        wp[o][i] = wproj[o * 128 + h * 16 + i];
    }
    __syncthreads();

    const int o  = tid >> 1;
    const int jb = (tid & 1) * 8;
    #pragma unroll
    for (int jj = 0; jj < 8; jj++) {
        const int j = jb + jj;
        float acc = 0.f;
        #pragma unroll
        for (int i = 0; i < 16; i++) acc += wp[o][i] * at[i][j];
        const __nv_bfloat16 hh = __float2bfloat16(acc);
        const __nv_bfloat16 ll = __float2bfloat16(acc - __bfloat162float(hh));
        const long oidx = ((long)z * 128 + o) * 128 + h * 16 + j;
        whi[oidx] = hh;
        wlo[oidx] = ll;
    }
}

// ===================== launch ===============================================
extern "C" void kernel_launch(void* const* d_in, const int* in_sizes, int n_in,
                              void* d_out, int out_size)
{
    const float* x_in   = (const float*)d_in[0];
    const float* illu   = (const float*)d_in[1];
    const float* w_qkv  = (const float*)d_in[2];
    const float* w_dw   = (const float*)d_in[3];
    const float* w_proj = (const float*)d_in[4];
    const float* temp   = (const float*)d_in[5];
    float* out = (float*)d_out;

    float *qkv, *qkv2, *part, *attn;
    __nv_bfloat16 *whi, *wlo, *wehi, *welo;
    cudaGetSymbolAddress((void**)&qkv,  g_qkv);
    cudaGetSymbolAddress((void**)&qkv2, g_qkv2);
    cudaGetSymbolAddress((void**)&part, g_part);
    cudaGetSymbolAddress((void**)&attn, g_attn);
    cudaGetSymbolAddress((void**)&whi,  g_whi);
    cudaGetSymbolAddress((void**)&wlo,  g_wlo);
    cudaGetSymbolAddress((void**)&wehi, g_wehi);
    cudaGetSymbolAddress((void**)&welo, g_welo);

    cudaFuncSetAttribute(gemm_cvt<false>, cudaFuncAttributeMaxDynamicSharedMemorySize, SM_GEMM);
    cudaFuncSetAttribute(gemm_cvt<true>,  cudaFuncAttributeMaxDynamicSharedMemorySize, SM_GEMM);
    cudaFuncSetAttribute(gram16, cudaFuncAttributeMaxDynamicSharedMemorySize, GR_SM);

    // 0) pre-split qkv weights
    cvt_split<<<QKV_CH * C_CH / 1024, 256>>>(w_qkv, whi, wlo);
    // 1) qkv = w_qkv @ x
    gemm_cvt<false><<<dim3(HW / 128, QKV_CH / 128, BATCH), 256, SM_GEMM>>>(
        whi, wlo, 0L, x_in, (long)C_CH * HW, nullptr, 0L, qkv, QKV_CH);
    // 2) depthwise 3x3 SAME
    dwconv3x3<<<dim3(4, BATCH * QKV_CH), 256>>>(qkv, w_dw, qkv2);
    // 3) gram partials + norms (cp.async double-buffered)
    gram16<<<dim3(NCHUNK, 64), 256, GR_SM>>>(qkv2, part);
    // 4) softmax
    attn_softmax<<<64, 256>>>(part, temp, attn);
    // 5) Weff[z] = W_proj @ blockdiag(attn[z])
    weff_build<<<64, 256>>>(w_proj, attn, wehi, welo);
    // 6) out = Weff[z] @ (v .* illu)
    gemm_cvt<true><<<dim3(HW / 128, 1, BATCH), 256, SM_GEMM>>>(
        wehi, welo, (long)C_CH * C_CH,
        qkv2 + 2L * C_CH * HW, (long)QKV_CH * HW,
        illu, (long)C_CH * HW, out, C_CH);
}

// round 15
// speedup vs baseline: 1.1661x; 1.0090x over previous
#include <cuda_runtime.h>
#include <cuda_bf16.h>
#include <cstdint>

#define C_CH   128
#define HW     16384
#define BATCH  8
#define QKV_CH 384
#define NHEAD  8
#define DH     16
#define NCHUNK 16

// ===================== scratch ==============================================
__device__ float g_qkv  [(long)BATCH * QKV_CH * HW];
__device__ float g_qkv2 [(long)BATCH * QKV_CH * HW];
__device__ float g_part [64 * NCHUNK * 288];
__device__ float g_attn [64 * 256];
__device__ __align__(16) __nv_bfloat16 g_whi   [QKV_CH * C_CH];
__device__ __align__(16) __nv_bfloat16 g_wlo   [QKV_CH * C_CH];
__device__ __align__(16) __nv_bfloat16 g_wehi  [BATCH * C_CH * C_CH];
__device__ __align__(16) __nv_bfloat16 g_welo  [BATCH * C_CH * C_CH];

// ===================== PTX helpers ==========================================
__device__ __forceinline__ uint32_t smem_u32(const void* p) {
    uint32_t a;
    asm("{ .reg .u64 t; cvta.to.shared.u64 t, %1; cvt.u32.u64 %0, t; }" : "=r"(a) : "l"(p));
    return a;
}
__device__ __forceinline__ void ldsm_x4(uint32_t* r, uint32_t addr) {
    asm volatile("ldmatrix.sync.aligned.m8n8.x4.shared.b16 {%0,%1,%2,%3}, [%4];"
                 : "=r"(r[0]), "=r"(r[1]), "=r"(r[2]), "=r"(r[3]) : "r"(addr));
}
__device__ __forceinline__ void ldsm_x4_t(uint32_t* r, uint32_t addr) {
    asm volatile("ldmatrix.sync.aligned.m8n8.x4.trans.shared.b16 {%0,%1,%2,%3}, [%4];"
                 : "=r"(r[0]), "=r"(r[1]), "=r"(r[2]), "=r"(r[3]) : "r"(addr));
}
__device__ __forceinline__ void mma_bf16(float* d, const uint32_t* a, const uint32_t* b) {
    asm volatile(
        "mma.sync.aligned.m16n8k16.row.col.f32.bf16.bf16.f32 "
        "{%0,%1,%2,%3}, {%4,%5,%6,%7}, {%8,%9}, {%0,%1,%2,%3};"
        : "+f"(d[0]), "+f"(d[1]), "+f"(d[2]), "+f"(d[3])
        : "r"(a[0]), "r"(a[1]), "r"(a[2]), "r"(a[3]), "r"(b[0]), "r"(b[1]));
}
__device__ __forceinline__ void cp_async16(uint32_t dst, const void* src) {
    asm volatile("cp.async.ca.shared.global [%0], [%1], 16;" :: "r"(dst), "l"(src));
}
#define CP_COMMIT() asm volatile("cp.async.commit_group;" ::: "memory")
#define CP_WAIT(n)  asm volatile("cp.async.wait_group %0;" :: "n"(n) : "memory")

__device__ __forceinline__ uint32_t split_hi2(float x, float y, float& rx, float& ry) {
    const __nv_bfloat16 hx = __float2bfloat16(x);
    const __nv_bfloat16 hy = __float2bfloat16(y);
    rx = x - __bfloat162float(hx);
    ry = y - __bfloat162float(hy);
    __nv_bfloat162 p; p.x = hx; p.y = hy;
    return *(uint32_t*)&p;
}
__device__ __forceinline__ uint32_t pack_bf2(float x, float y) {
    __nv_bfloat162 p; p.x = __float2bfloat16(x); p.y = __float2bfloat16(y);
    return *(uint32_t*)&p;
}

// ===================== split kernel (weights) ================================
__global__ void __launch_bounds__(256) cvt_split(
    const float* __restrict__ in,
    __nv_bfloat16* __restrict__ hi, __nv_bfloat16* __restrict__ lo)
{
    const long i4 = (long)blockIdx.x * 256 + threadIdx.x;
    const float4 v = ((const float4*)in)[i4];
    float lx, ly, lz, lw;
    const uint32_t h0 = split_hi2(v.x, v.y, lx, ly);
    const uint32_t h1 = split_hi2(v.z, v.w, lz, lw);
    ((uint2*)hi)[i4] = make_uint2(h0, h1);
    ((uint2*)lo)[i4] = make_uint2(pack_bf2(lx, ly), pack_bf2(lz, lw));
}

// ===================== unified GEMM (round-8 config) =========================
#define WS      136
#define XS      136
#define S_WHI   0
#define S_WLO   34816
#define S_XHI   69632
#define S_XLO   78336
#define SM_GEMM 87040

template<bool GATED>
__global__ void __launch_bounds__(256, 2) gemm_cvt(
    const __nv_bfloat16* __restrict__ Whi_g, const __nv_bfloat16* __restrict__ Wlo_g,
    long wz,
    const float* __restrict__ Xg, long xz,
    const float* __restrict__ Ig, long iz,
    float* __restrict__ Cg, int Mw)
{
    extern __shared__ char sm[];
    const uint32_t smb = smem_u32(sm);

    const int tid  = threadIdx.x;
    const int lane = tid & 31;
    const int wid  = tid >> 5;
    const int wm   = wid >> 2;
    const int wn   = wid & 3;
    const int n0   = blockIdx.x * 128;
    const int m0   = blockIdx.y * 128;
    const int z    = blockIdx.z;

    const __nv_bfloat16* Whi = Whi_g + (long)z * wz;
    const __nv_bfloat16* Wlo = Wlo_g + (long)z * wz;
    const float* X = Xg + (long)z * xz;
    const float* I = GATED ? (Ig + (long)z * iz) : nullptr;
    float* C = Cg + (long)z * (long)Mw * HW;

    #pragma unroll
    for (int t = 0; t < 16; t++) {
        const int lin = t * 256 + tid;
        const int spl = lin >> 11;
        const int row = (lin >> 4) & 127;
        const int seg = lin & 15;
        const __nv_bfloat16* src = (spl ? Wlo : Whi) + (long)(m0 + row) * 128 + seg * 8;
        const uint32_t dst = smb + (spl ? S_WLO : S_WHI) + (row * WS + seg * 8) * 2;
        cp_async16(dst, src);
    }
    CP_COMMIT();

    float acc[4][4][4];
    #pragma unroll
    for (int i = 0; i < 4; i++)
        #pragma unroll
        for (int j = 0; j < 4; j++)
            #pragma unroll
            for (int r = 0; r < 4; r++) acc[i][j][r] = 0.f;

    const int a_row = (lane & 7) + ((lane >> 3) & 1) * 8;
    const int a_col = (lane >> 4) * 8;
    const int b_row = (lane & 7) + ((lane >> 3) & 1) * 8;
    const int b_col = (lane >> 4) * 8;

    const int r0 = tid >> 5;
    const int c4 = (tid & 31) * 4;

    float4 xs[4], is_[4];
    #pragma unroll
    for (int rr = 0; rr < 4; rr++) {
        const int grow = r0 + rr * 8;
        xs[rr] = *(const float4*)(X + (long)grow * HW + n0 + c4);
        if (GATED) is_[rr] = *(const float4*)(I + (long)grow * HW + n0 + c4);
    }
    CP_WAIT(0);

    #pragma unroll
    for (int kc = 0; kc < 4; kc++) {
        #pragma unroll
        for (int rr = 0; rr < 4; rr++) {
            float4 v = xs[rr];
            if (GATED) { v.x *= is_[rr].x; v.y *= is_[rr].y; v.z *= is_[rr].z; v.w *= is_[rr].w; }
            float lx, ly, lz, lw;
            const uint32_t h0 = split_hi2(v.x, v.y, lx, ly);
            const uint32_t h1 = split_hi2(v.z, v.w, lz, lw);
            const int row = r0 + rr * 8;
            const uint32_t off = (uint32_t)(row * XS + c4) * 2;
            *(uint2*)(sm + S_XHI + off) = make_uint2(h0, h1);
            *(uint2*)(sm + S_XLO + off) = make_uint2(pack_bf2(lx, ly), pack_bf2(lz, lw));
        }
        __syncthreads();

        if (kc < 3) {
            #pragma unroll
            for (int rr = 0; rr < 4; rr++) {
                const int grow = (kc + 1) * 32 + r0 + rr * 8;
                xs[rr] = *(const float4*)(X + (long)grow * HW + n0 + c4);
                if (GATED) is_[rr] = *(const float4*)(I + (long)grow * HW + n0 + c4);
            }
        }

        #pragma unroll
        for (int ks = 0; ks < 2; ks++) {
            const int kk  = ks * 16;
            const int kkg = kc * 32 + kk;
            uint32_t a[4][4], bh[2][4], bl[2][4];

            #pragma unroll
            for (int u = 0; u < 2; u++) {
                const int r = kk + b_row;
                const int c = wn * 32 + u * 16 + b_col;
                ldsm_x4_t(bh[u], smb + S_XHI + (r * XS + c) * 2);
                ldsm_x4_t(bl[u], smb + S_XLO + (r * XS + c) * 2);
            }
            #pragma unroll
            for (int i = 0; i < 4; i++) {
                const int r = wm * 64 + i * 16 + a_row;
                ldsm_x4(a[i], smb + S_WHI + (r * WS + kkg + a_col) * 2);
            }
            #pragma unroll
            for (int i = 0; i < 4; i++)
                #pragma unroll
                for (int j = 0; j < 4; j++)
                    mma_bf16(acc[i][j], a[i], &bh[j >> 1][(j & 1) * 2]);
            #pragma unroll
            for (int i = 0; i < 4; i++)
                #pragma unroll
                for (int j = 0; j < 4; j++)
                    mma_bf16(acc[i][j], a[i], &bl[j >> 1][(j & 1) * 2]);
            #pragma unroll
            for (int i = 0; i < 4; i++) {
                const int r = wm * 64 + i * 16 + a_row;
                ldsm_x4(a[i], smb + S_WLO + (r * WS + kkg + a_col) * 2);
            }
            #pragma unroll
            for (int i = 0; i < 4; i++)
                #pragma unroll
                for (int j = 0; j < 4; j++)
                    mma_bf16(acc[i][j], a[i], &bh[j >> 1][(j & 1) * 2]);
        }
        __syncthreads();
    }

    const int mw = m0 + wm * 64;
    const int nw = n0 + wn * 32;
    #pragma unroll
    for (int i = 0; i < 4; i++) {
        #pragma unroll
        for (int j = 0; j < 4; j++) {
            const int row0 = mw + i * 16 + (lane >> 2);
            const int col  = nw + j * 8 + (lane & 3) * 2;
            *(float2*)&C[(long)row0 * HW + col]       = make_float2(acc[i][j][0], acc[i][j][1]);
            *(float2*)&C[(long)(row0 + 8) * HW + col] = make_float2(acc[i][j][2], acc[i][j][3]);
        }
    }
}

// ===================== depthwise 3x3 (32 rows/block, all 384 channels) =======
__global__ void __launch_bounds__(256) dwconv3x3(
    const float* __restrict__ in, const float* __restrict__ w, float* __restrict__ out)
{
    __shared__ float s[34][128];

    const int bc = blockIdx.y;
    const int y0 = blockIdx.x * 32;
    const int ch = bc % QKV_CH;
    const int tid = threadIdx.x;
    const float* ip = in + (long)bc * HW;

    for (int t = tid; t < 1088; t += 256) {
        const int r  = t >> 5;
        const int c4 = (t & 31) * 4;
        const int gy = y0 - 1 + r;
        float4 v = make_float4(0.f, 0.f, 0.f, 0.f);
        if (gy >= 0 && gy < 128) v = *(const float4*)&ip[gy * 128 + c4];
        *(float4*)&s[r][c4] = v;
    }

    const float* wp = w + ch * 9;
    const float w00 = wp[0], w01 = wp[1], w02 = wp[2];
    const float w10 = wp[3], w11 = wp[4], w12 = wp[5];
    const float w20 = wp[6], w21 = wp[7], w22 = wp[8];
    __syncthreads();

    const int x = (tid & 31) * 4;
    #pragma unroll
    for (int h = 0; h < 4; h++) {
        const int oy = (tid >> 5) + h * 8;
        float o0 = 0.f, o1 = 0.f, o2 = 0.f, o3 = 0.f;
        #pragma unroll
        for (int dy = 0; dy < 3; dy++) {
            const float* row = s[oy + dy];
            const float4 v = *(const float4*)&row[x];
            const float vl = (x > 0)   ? row[x - 1] : 0.f;
            const float vr = (x < 124) ? row[x + 4] : 0.f;
            const float wa = (dy == 0) ? w00 : (dy == 1) ? w10 : w20;
            const float wb = (dy == 0) ? w01 : (dy == 1) ? w11 : w21;
            const float wc = (dy == 0) ? w02 : (dy == 1) ? w12 : w22;
            o0 += vl  * wa + v.x * wb + v.y * wc;
            o1 += v.x * wa + v.y * wb + v.z * wc;
            o2 += v.y * wa + v.z * wb + v.w * wc;
            o3 += v.z * wa + v.w * wb + vr  * wc;
        }
        *(float4*)&out[(long)bc * HW + (y0 + oy) * 128 + x] = make_float4(o0, o1, o2, o3);
    }
}

// ===================== gram partials (2x4 tile, 4 CTAs/SM) ===================
// smem: 2 stages x (q[16][132] + k[16][132]) = 33792 B
#define GR_STG  16896
#define GR_K    8448
#define GR_SM   33792

__global__ void __launch_bounds__(256, 4) gram16(
    const float* __restrict__ qkv2, float* __restrict__ partials)
{
    extern __shared__ char gsm[];
    const uint32_t gsb = smem_u32(gsm);

    const int bh = blockIdx.y;
    const int b  = bh >> 3, hd = bh & 7;
    const int n0 = blockIdx.x * 1024;
    const float* qg = qkv2 + (long)b * QKV_CH * HW + (long)hd * DH * HW + n0;
    const float* kg = qg + (long)C_CH * HW;

    const int tid = threadIdx.x;
    // compute mapping: 2(q) x 4(k) tile, 8 t-slices
    const int tt = tid & 7;                // t-slice
    const int jj = (tid >> 3) & 3;         // k-group (4 rows)
    const int ii = tid >> 5;               // q-group (2 rows)

    // staging: each thread copies 2 float4 per tensor per chunk
    const int sr = tid >> 4;
    const int sc = (tid & 15) * 8;

    auto load_stage = [&](int stg, int t0) {
        const uint32_t base = gsb + (uint32_t)stg * GR_STG;
        const uint32_t qoff = base + (sr * 132 + sc) * 4;
        const uint32_t koff = base + GR_K + (sr * 132 + sc) * 4;
        cp_async16(qoff,      qg + (long)sr * HW + t0 + sc);
        cp_async16(qoff + 16, qg + (long)sr * HW + t0 + sc + 4);
        cp_async16(koff,      kg + (long)sr * HW + t0 + sc);
        cp_async16(koff + 16, kg + (long)sr * HW + t0 + sc + 4);
    };

    float acc[2][4];
    #pragma unroll
    for (int a = 0; a < 2; a++)
        #pragma unroll
        for (int c = 0; c < 4; c++) acc[a][c] = 0.f;
    float nq[2] = {0.f, 0.f};
    float nk[4] = {0.f, 0.f, 0.f, 0.f};

    load_stage(0, 0);
    CP_COMMIT();

    #pragma unroll
    for (int cidx = 0; cidx < 8; cidx++) {
        if (cidx < 7) {
            load_stage((cidx + 1) & 1, (cidx + 1) * 128);
            CP_COMMIT();
            CP_WAIT(1);
        } else {
            CP_WAIT(0);
        }
        __syncthreads();

        const float* qs = (const float*)(gsm + (cidx & 1) * GR_STG);
        const float* ks = (const float*)(gsm + (cidx & 1) * GR_STG + GR_K);

        #pragma unroll
        for (int u = 0; u < 4; u++) {
            const int c4 = (u * 8 + tt) * 4;          // 32 float4 slots over 128 cols
            float4 q4[2], k4[4];
            #pragma unroll
            for (int r = 0; r < 2; r++) q4[r] = *(const float4*)&qs[(ii * 2 + r) * 132 + c4];
            #pragma unroll
            for (int r = 0; r < 4; r++) k4[r] = *(const float4*)&ks[(jj * 4 + r) * 132 + c4];
            #pragma unroll
            for (int a = 0; a < 2; a++)
                #pragma unroll
                for (int c = 0; c < 4; c++)
                    acc[a][c] += q4[a].x * k4[c].x + q4[a].y * k4[c].y
                               + q4[a].z * k4[c].z + q4[a].w * k4[c].w;
            if (jj == 0) {
                #pragma unroll
                for (int r = 0; r < 2; r++)
                    nq[r] += q4[r].x * q4[r].x + q4[r].y * q4[r].y
                           + q4[r].z * q4[r].z + q4[r].w * q4[r].w;
            }
            if (ii == 0) {
                #pragma unroll
                for (int r = 0; r < 4; r++)
                    nk[r] += k4[r].x * k4[r].x + k4[r].y * k4[r].y
                           + k4[r].z * k4[r].z + k4[r].w * k4[r].w;
            }
        }
        __syncthreads();
    }

    // butterfly reduce over tt (3 lane bits; within-warp)
    #pragma unroll
    for (int m = 1; m < 8; m <<= 1) {
        #pragma unroll
        for (int a = 0; a < 2; a++)
            #pragma unroll
            for (int c = 0; c < 4; c++)
                acc[a][c] += __shfl_xor_sync(0xFFFFFFFFu, acc[a][c], m);
        #pragma unroll
        for (int r = 0; r < 2; r++) nq[r] += __shfl_xor_sync(0xFFFFFFFFu, nq[r], m);
        #pragma unroll
        for (int r = 0; r < 4; r++) nk[r] += __shfl_xor_sync(0xFFFFFFFFu, nk[r], m);
    }

    float* p = partials + ((long)bh * NCHUNK + blockIdx.x) * 288;
    if (tt == 0) {
        #pragma unroll
        for (int a = 0; a < 2; a++)
            #pragma unroll
            for (int c = 0; c < 4; c++)
                p[(ii * 2 + a) * 16 + jj * 4 + c] = acc[a][c];
        if (jj == 0) {
            #pragma unroll
            for (int r = 0; r < 2; r++) p[256 + ii * 2 + r] = nq[r];
        }
        if (ii == 0) {
            #pragma unroll
            for (int r = 0; r < 4; r++) p[256 + 16 + jj * 4 + r] = nk[r];
        }
    }
}

// ===================== softmax ==============================================
__global__ void __launch_bounds__(256) attn_softmax(
    const float* __restrict__ partials, const float* __restrict__ temperature,
    float* __restrict__ attn)
{
    const int bh = blockIdx.x;
    const int hd = bh & 7;
    __shared__ float S[256];
    __shared__ float qn[16], kn[16];
    const int tid = threadIdx.x;
    float s = 0.f;
    #pragma unroll
    for (int c = 0; c < NCHUNK; c++)
        s += partials[((long)bh * NCHUNK + c) * 288 + tid];
    S[tid] = s;
    if (tid < 32) {
        float ns = 0.f;
        #pragma unroll
        for (int c = 0; c < NCHUNK; c++)
            ns += partials[((long)bh * NCHUNK + c) * 288 + 256 + tid];
        const float nv = fmaxf(sqrtf(ns), 1e-12f);
        if (tid < 16) qn[tid] = nv; else kn[tid - 16] = nv;
    }
    __syncthreads();
    if (tid < 16) {
        const int   i  = tid;
        const float tp = temperature[hd];
        float lg[16];
        float mx = -1e30f;
        #pragma unroll
        for (int j = 0; j < 16; j++) {
            lg[j] = S[i * 16 + j] / (qn[i] * kn[j]) * tp;
            mx = fmaxf(mx, lg[j]);
        }
        float sum = 0.f;
        #pragma unroll
        for (int j = 0; j < 16; j++) { lg[j] = expf(lg[j] - mx); sum += lg[j]; }
        const float inv = 1.f / sum;
        #pragma unroll
        for (int j = 0; j < 16; j++)
            attn[(long)bh * 256 + i * 16 + j] = lg[j] * inv;
    }
}

// ===================== Weff = W_proj @ blockdiag(attn) ======================
__global__ void __launch_bounds__(256) weff_build(
    const float* __restrict__ wproj, const float* __restrict__ attn,
    __nv_bfloat16* __restrict__ whi, __nv_bfloat16* __restrict__ wlo)
{
    const int bh = blockIdx.x;
    const int h  = bh & 7, z = bh >> 3;
    __shared__ float at[16][16];
    __shared__ float wp[128][17];
    const int tid = threadIdx.x;

    at[tid >> 4][tid & 15] = attn[(long)bh * 256 + tid];
    #pragma unroll
    for (int t = 0; t < 8; t++) {
        const int idx = t * 256 + tid;
        const int o = idx >> 4, i = idx & 15;
        wp[o][i] = wproj[o * 128 + h * 16 + i];
    }
    __syncthreads();

    const int o  = tid >> 1;
    const int jb = (tid & 1) * 8;
    #pragma unroll
    for (int jj = 0; jj < 8; jj++) {
        const int j = jb + jj;
        float acc = 0.f;
        #pragma unroll
        for (int i = 0; i < 16; i++) acc += wp[o][i] * at[i][j];
        const __nv_bfloat16 hh = __float2bfloat16(acc);
        const __nv_bfloat16 ll = __float2bfloat16(acc - __bfloat162float(hh));
        const long oidx = ((long)z * 128 + o) * 128 + h * 16 + j;
        whi[oidx] = hh;
        wlo[oidx] = ll;
    }
}

// ===================== launch ===============================================
extern "C" void kernel_launch(void* const* d_in, const int* in_sizes, int n_in,
                              void* d_out, int out_size)
{
    const float* x_in   = (const float*)d_in[0];
    const float* illu   = (const float*)d_in[1];
    const float* w_qkv  = (const float*)d_in[2];
    const float* w_dw   = (const float*)d_in[3];
    const float* w_proj = (const float*)d_in[4];
    const float* temp   = (const float*)d_in[5];
    float* out = (float*)d_out;

    float *qkv, *qkv2, *part, *attn;
    __nv_bfloat16 *whi, *wlo, *wehi, *welo;
    cudaGetSymbolAddress((void**)&qkv,  g_qkv);
    cudaGetSymbolAddress((void**)&qkv2, g_qkv2);
    cudaGetSymbolAddress((void**)&part, g_part);
    cudaGetSymbolAddress((void**)&attn, g_attn);
    cudaGetSymbolAddress((void**)&whi,  g_whi);
    cudaGetSymbolAddress((void**)&wlo,  g_wlo);
    cudaGetSymbolAddress((void**)&wehi, g_wehi);
    cudaGetSymbolAddress((void**)&welo, g_welo);

    cudaFuncSetAttribute(gemm_cvt<false>, cudaFuncAttributeMaxDynamicSharedMemorySize, SM_GEMM);
    cudaFuncSetAttribute(gemm_cvt<true>,  cudaFuncAttributeMaxDynamicSharedMemorySize, SM_GEMM);
    cudaFuncSetAttribute(gram16, cudaFuncAttributeMaxDynamicSharedMemorySize, GR_SM);

    // 0) pre-split qkv weights
    cvt_split<<<QKV_CH * C_CH / 1024, 256>>>(w_qkv, whi, wlo);
    // 1) qkv = w_qkv @ x
    gemm_cvt<false><<<dim3(HW / 128, QKV_CH / 128, BATCH), 256, SM_GEMM>>>(
        whi, wlo, 0L, x_in, (long)C_CH * HW, nullptr, 0L, qkv, QKV_CH);
    // 2) depthwise 3x3 SAME
    dwconv3x3<<<dim3(4, BATCH * QKV_CH), 256>>>(qkv, w_dw, qkv2);
    // 3) gram partials + norms (2x4 tile, higher occupancy)
    gram16<<<dim3(NCHUNK, 64), 256, GR_SM>>>(qkv2, part);
    // 4) softmax
    attn_softmax<<<64, 256>>>(part, temp, attn);
    // 5) Weff[z] = W_proj @ blockdiag(attn[z])
    weff_build<<<64, 256>>>(w_proj, attn, wehi, welo);
    // 6) out = Weff[z] @ (v .* illu)
    gemm_cvt<true><<<dim3(HW / 128, 1, BATCH), 256, SM_GEMM>>>(
        wehi, welo, (long)C_CH * C_CH,
        qkv2 + 2L * C_CH * HW, (long)QKV_CH * HW,
        illu, (long)C_CH * HW, out, C_CH);
}